// round 1
// baseline (speedup 1.0000x reference)
#include <cuda_runtime.h>
#include <math.h>

#define HEADS 16
#define HDIM  64
#define BATCH 2
#define TLEN  2048
#define EDIM  1024
#define MROWS (BATCH*TLEN)   // 4096

// Scratch (allocation-free rule: __device__ globals)
__device__ float g_q[MROWS*EDIM];
__device__ float g_k[MROWS*EDIM];
__device__ float g_v[MROWS*EDIM];
__device__ float g_att[MROWS*EDIM];

// ---------------------------------------------------------------------------
// SGEMM: C[M,N] = A[M,K] @ B[K,N] (+ bias[N] if bias != nullptr)
// BM=BN=128, BK=8, 256 threads, 8x8 per thread. All dims divisible.
// ---------------------------------------------------------------------------
__global__ __launch_bounds__(256, 2)
void sgemm128(const float* __restrict__ A, const float* __restrict__ Bm,
              const float* __restrict__ bias, float* __restrict__ C,
              int M, int N, int K)
{
    const int BM = 128, BN = 128, BK = 8;
    __shared__ float As[BK][BM];
    __shared__ float Bs[BK][BN];

    int tid  = threadIdx.x;
    int bcol = blockIdx.x;   // N tiles
    int brow = blockIdx.y;   // M tiles

    const float* Ab = A  + (size_t)brow * BM * K;
    const float* Bb = Bm + (size_t)bcol * BN;
    float*       Cb = C  + (size_t)brow * BM * N + (size_t)bcol * BN;

    int aRow = tid >> 1;          // 0..127
    int aCol = (tid & 1) * 4;     // 0 or 4
    int bRow = tid >> 5;          // 0..7
    int bCol = (tid & 31) * 4;    // 0..124

    int tr = (tid >> 4) * 8;      // thread row base (0..120)
    int tc = (tid & 15) * 8;      // thread col base (0..120)

    float acc[8][8];
    #pragma unroll
    for (int i = 0; i < 8; i++)
        #pragma unroll
        for (int j = 0; j < 8; j++) acc[i][j] = 0.f;

    float ra[8], rb[8];

    for (int k0 = 0; k0 < K; k0 += BK) {
        float4 av = *(const float4*)(Ab + (size_t)aRow * K + k0 + aCol);
        As[aCol + 0][aRow] = av.x;
        As[aCol + 1][aRow] = av.y;
        As[aCol + 2][aRow] = av.z;
        As[aCol + 3][aRow] = av.w;
        float4 bv = *(const float4*)(Bb + (size_t)(k0 + bRow) * N + bCol);
        *(float4*)(&Bs[bRow][bCol]) = bv;
        __syncthreads();

        #pragma unroll
        for (int k = 0; k < BK; k++) {
            #pragma unroll
            for (int i = 0; i < 8; i++) ra[i] = As[k][tr + i];
            #pragma unroll
            for (int j = 0; j < 8; j++) rb[j] = Bs[k][tc + j];
            #pragma unroll
            for (int i = 0; i < 8; i++)
                #pragma unroll
                for (int j = 0; j < 8; j++)
                    acc[i][j] += ra[i] * rb[j];
        }
        __syncthreads();
    }

    #pragma unroll
    for (int i = 0; i < 8; i++) {
        #pragma unroll
        for (int j = 0; j < 8; j += 4) {
            float4 o;
            o.x = acc[i][j + 0];
            o.y = acc[i][j + 1];
            o.z = acc[i][j + 2];
            o.w = acc[i][j + 3];
            if (bias) {
                const float* bp = bias + (size_t)bcol * BN + tc + j;
                o.x += bp[0]; o.y += bp[1]; o.z += bp[2]; o.w += bp[3];
            }
            *(float4*)(Cb + (size_t)(tr + i) * N + tc + j) = o;
        }
    }
}

// ---------------------------------------------------------------------------
// Per-head LayerNorm over head dim (64). One warp per row of 64.
// ---------------------------------------------------------------------------
__global__ __launch_bounds__(256)
void head_layernorm(float* __restrict__ x, const float* __restrict__ w,
                    const float* __restrict__ b, int nrows)
{
    int warp = (blockIdx.x * blockDim.x + threadIdx.x) >> 5;
    int lane = threadIdx.x & 31;
    if (warp >= nrows) return;
    float* row = x + (size_t)warp * HDIM;
    float v0 = row[lane];
    float v1 = row[lane + 32];
    float s = v0 + v1;
    #pragma unroll
    for (int o = 16; o > 0; o >>= 1) s += __shfl_xor_sync(0xffffffffu, s, o);
    float mu = s * (1.f / 64.f);
    float d0 = v0 - mu, d1 = v1 - mu;
    float vs = d0 * d0 + d1 * d1;
    #pragma unroll
    for (int o = 16; o > 0; o >>= 1) vs += __shfl_xor_sync(0xffffffffu, vs, o);
    float inv = rsqrtf(vs * (1.f / 64.f) + 1e-5f);
    row[lane]      = d0 * inv * w[lane]      + b[lane];
    row[lane + 32] = d1 * inv * w[lane + 32] + b[lane + 32];
}

// ---------------------------------------------------------------------------
// Causal flash attention. Q tile = 64 rows, KV tile = 32 rows.
// 256 threads: c4 = tid&3 (col group), r = tid>>2 (q row in tile).
// Same-r threads are 4 consecutive lanes -> shuffle reductions over width 4.
// ---------------------------------------------------------------------------
__global__ __launch_bounds__(256)
void flash_attn(const float* __restrict__ Q, const float* __restrict__ Kp,
                const float* __restrict__ V, float* __restrict__ O)
{
    const int TQ = 64, TK = 32;
    __shared__ float Qs[TQ][HDIM + 1];
    __shared__ float Ks[TK][HDIM + 1];
    __shared__ float Vs[TK][HDIM];
    __shared__ float Ps[TQ][TK + 1];

    int qt = blockIdx.x;   // 0..31
    int h  = blockIdx.y;   // 0..15
    int bb = blockIdx.z;   // 0..1
    int tid = threadIdx.x;
    int c4  = tid & 3;
    int r   = tid >> 2;

    int q0 = qt * TQ;
    int qg = q0 + r;

    // Load Q tile (coalesced over d)
    for (int i = tid; i < TQ * HDIM; i += 256) {
        int rr = i >> 6, d = i & 63;
        Qs[rr][d] = Q[(size_t)(bb * TLEN + q0 + rr) * EDIM + h * HDIM + d];
    }

    float acc[16];
    #pragma unroll
    for (int j = 0; j < 16; j++) acc[j] = 0.f;
    float m = -INFINITY, l = 0.f;

    int nkt = 2 * qt + 2;
    for (int kt = 0; kt < nkt; kt++) {
        __syncthreads();   // protect Ks/Vs from previous-iteration readers
        int k0 = kt * TK;
        for (int i = tid; i < TK * HDIM; i += 256) {
            int rr = i >> 6, d = i & 63;
            size_t gi = (size_t)(bb * TLEN + k0 + rr) * EDIM + h * HDIM + d;
            Ks[rr][d] = Kp[gi];
            Vs[rr][d] = V[gi];
        }
        __syncthreads();

        // S = Q K^T for this thread's 8 k-columns
        float s[8];
        #pragma unroll
        for (int j = 0; j < 8; j++) s[j] = 0.f;
        int kc0 = c4 * 8;
        #pragma unroll 8
        for (int d = 0; d < HDIM; d++) {
            float qv = Qs[r][d];
            #pragma unroll
            for (int j = 0; j < 8; j++) s[j] += qv * Ks[kc0 + j][d];
        }

        // scale + causal mask + local max
        float mloc = -INFINITY;
        #pragma unroll
        for (int j = 0; j < 8; j++) {
            s[j] *= 0.125f;                       // 1/sqrt(64)
            if (k0 + kc0 + j > qg) s[j] = -INFINITY;
            mloc = fmaxf(mloc, s[j]);
        }
        mloc = fmaxf(mloc, __shfl_xor_sync(0xffffffffu, mloc, 1));
        mloc = fmaxf(mloc, __shfl_xor_sync(0xffffffffu, mloc, 2));
        float mnew = fmaxf(m, mloc);

        float lloc = 0.f;
        #pragma unroll
        for (int j = 0; j < 8; j++) {
            float p = __expf(s[j] - mnew);        // -inf -> 0
            Ps[r][kc0 + j] = p;
            lloc += p;
        }
        lloc += __shfl_xor_sync(0xffffffffu, lloc, 1);
        lloc += __shfl_xor_sync(0xffffffffu, lloc, 2);

        float corr = __expf(m - mnew);            // m=-inf first iter -> 0
        l = l * corr + lloc;
        m = mnew;
        #pragma unroll
        for (int j = 0; j < 16; j++) acc[j] *= corr;
        __syncthreads();

        // O += P @ V; this thread owns cols {c4 + 4*j} (bank-conflict-free)
        #pragma unroll 4
        for (int k = 0; k < TK; k++) {
            float p = Ps[r][k];
            #pragma unroll
            for (int j = 0; j < 16; j++) acc[j] += p * Vs[k][c4 + 4 * j];
        }
    }

    float inv = 1.f / l;
    size_t ob = (size_t)(bb * TLEN + q0 + r) * EDIM + h * HDIM;
    #pragma unroll
    for (int j = 0; j < 16; j++)
        O[ob + c4 + 4 * j] = acc[j] * inv;
}

// ---------------------------------------------------------------------------
// Launch
// ---------------------------------------------------------------------------
extern "C" void kernel_launch(void* const* d_in, const int* in_sizes, int n_in,
                              void* d_out, int out_size)
{
    const float* x     = (const float*)d_in[0];
    const float* Wk    = (const float*)d_in[1];
    const float* Wq    = (const float*)d_in[2];
    const float* Wv    = (const float*)d_in[3];
    const float* Wo    = (const float*)d_in[4];
    const float* bo    = (const float*)d_in[5];
    const float* kln_w = (const float*)d_in[6];
    const float* kln_b = (const float*)d_in[7];
    const float* qln_w = (const float*)d_in[8];
    const float* qln_b = (const float*)d_in[9];
    float* out = (float*)d_out;

    float *q, *k, *v, *att;
    cudaGetSymbolAddress((void**)&q,   g_q);
    cudaGetSymbolAddress((void**)&k,   g_k);
    cudaGetSymbolAddress((void**)&v,   g_v);
    cudaGetSymbolAddress((void**)&att, g_att);

    dim3 gemmGrid(EDIM / 128, MROWS / 128);   // (8, 32)
    sgemm128<<<gemmGrid, 256>>>(x, Wq, nullptr, q, MROWS, EDIM, EDIM);
    sgemm128<<<gemmGrid, 256>>>(x, Wk, nullptr, k, MROWS, EDIM, EDIM);
    sgemm128<<<gemmGrid, 256>>>(x, Wv, nullptr, v, MROWS, EDIM, EDIM);

    int nrows = MROWS * HEADS;                // 65536 rows of 64
    int lnBlocks = nrows * 32 / 256;          // 8192
    head_layernorm<<<lnBlocks, 256>>>(q, qln_w, qln_b, nrows);
    head_layernorm<<<lnBlocks, 256>>>(k, kln_w, kln_b, nrows);

    dim3 attGrid(TLEN / 64, HEADS, BATCH);    // (32, 16, 2)
    flash_attn<<<attGrid, 256>>>(q, k, v, att);

    sgemm128<<<gemmGrid, 256>>>(att, Wo, bo, out, MROWS, EDIM, EDIM);
}